// round 15
// baseline (speedup 1.0000x reference)
#include <cuda_runtime.h>
#include <cuda_fp16.h>

#define N_USERS 100000
#define N_ITEMS 200000
#define N_NODES (N_USERS + N_ITEMS)
#define NNZ     9600000
#define DIM     64
#define TOTAL   ((size_t)N_NODES * DIM)
#define TOTAL4  (TOTAL / 4)
#define CAP     128                     // slots/row; mean degree 32, ~17 sigma
#define WARPS_PER_BLOCK 8

// Scratch (__device__ globals, alloc-free rule).
// h0 = fp16(e0), h1 = e1, h2 = e2. Final combine reads fp32 inputs directly.
__device__ __align__(16) __half g_h0[TOTAL];
__device__ __align__(16) __half g_h1[TOTAL];
__device__ __align__(16) __half g_h2[TOTAL];
__device__ __align__(16) int2   g_bucket[(size_t)N_NODES * CAP];
__device__ int g_cnt[N_NODES];

// ---------------------------------------------------------------------------
// init: g_h0 = fp16(concat(user,item)); g_cnt = 0.
// ---------------------------------------------------------------------------
__global__ __launch_bounds__(256) void init_kernel(
    const float* __restrict__ user_emb,
    const float* __restrict__ item_emb)
{
    size_t i = (size_t)blockIdx.x * blockDim.x + threadIdx.x;
    if (i < N_NODES) g_cnt[i] = 0;
    if (i >= TOTAL4) return;
    const size_t ub = (size_t)N_USERS * DIM / 4;
    float4 v = (i < ub) ? ((const float4*)user_emb)[i]
                        : ((const float4*)item_emb)[i - ub];
    uint2 h;
    __half2 h01 = __floats2half2_rn(v.x, v.y);
    __half2 h23 = __floats2half2_rn(v.z, v.w);
    h.x = *(unsigned*)&h01;
    h.y = *(unsigned*)&h23;
    ((uint2*)g_h0)[i] = h;
}

// ---------------------------------------------------------------------------
// Single-pass bucketing, 4 edges/thread via int4 loads (NNZ % 4 == 0).
// Entry: (col, fp32 weight bits).
// ---------------------------------------------------------------------------
__global__ __launch_bounds__(256) void bucket_kernel(
    const int*   __restrict__ rows,
    const int*   __restrict__ cols,
    const float* __restrict__ vals)
{
    int t = blockIdx.x * blockDim.x + threadIdx.x;
    int e = t * 4;
    if (e >= NNZ) return;
    int4 r4 = __ldcs((const int4*)(rows + e));
    int4 c4 = __ldcs((const int4*)(cols + e));
    int4 v4 = __ldcs((const int4*)(vals + e));
    int rr[4] = {r4.x, r4.y, r4.z, r4.w};
    int cc[4] = {c4.x, c4.y, c4.z, c4.w};
    int vv[4] = {v4.x, v4.y, v4.z, v4.w};
    #pragma unroll
    for (int k = 0; k < 4; k++) {
        int pos = atomicAdd(&g_cnt[rr[k]], 1);
        if (pos < CAP)
            g_bucket[(size_t)rr[k] * CAP + pos] = make_int2(cc[k], vv[k]);
    }
}

// ---------------------------------------------------------------------------
// Warp-per-row segment sum, quad-edge gathers:
//  - meta staged in smem (+3 zero-weight pad entries -> branch-free tail)
//  - lane group g = lane>>3 handles edge i+g; each lane gathers uint4
//    (8 halfs = 8 dims) -> one warp LDG.128 instruction covers FOUR edges
//  - fp32 float[8] accumulator per lane; shfl_xor(8)+shfl_xor(16) merges
//    the 4 group partials; lanes 0-7 then hold the full row.
// ---------------------------------------------------------------------------
__device__ __forceinline__ void quad_step(
    const uint4* __restrict__ srcl, const int2* __restrict__ sm,
    int i, int grp, float* acc)
{
    int2 m = sm[i + grp];                              // LDS.64, grouped bcast
    uint4 x = __ldg(srcl + (size_t)m.x * (DIM / 8));   // 16B of row m.x
    float v = __int_as_float(m.y);
    float2 a = __half22float2(*(const __half2*)&x.x);
    float2 b = __half22float2(*(const __half2*)&x.y);
    float2 c = __half22float2(*(const __half2*)&x.z);
    float2 d = __half22float2(*(const __half2*)&x.w);
    acc[0] = fmaf(a.x, v, acc[0]);
    acc[1] = fmaf(a.y, v, acc[1]);
    acc[2] = fmaf(b.x, v, acc[2]);
    acc[3] = fmaf(b.y, v, acc[3]);
    acc[4] = fmaf(c.x, v, acc[4]);
    acc[5] = fmaf(c.y, v, acc[5]);
    acc[6] = fmaf(d.x, v, acc[6]);
    acc[7] = fmaf(d.y, v, acc[7]);
}

// After return, lanes 0-7 hold the row sum for dims [8*lane .. 8*lane+7].
__device__ __forceinline__ void row_segsum(
    const __half* __restrict__ src, int2* __restrict__ sm, int row, int lane,
    float* acc)
{
    int cnt = __ldg(&g_cnt[row]);
    if (cnt > CAP) cnt = CAP;
    const int2* ep = g_bucket + (size_t)row * CAP;

    // Stage meta into smem (coalesced) + 3 pad entries (zero weight).
    for (int b = lane; b < cnt; b += 32)
        sm[b] = __ldg(ep + b);
    if (lane < 3)
        sm[cnt + lane] = make_int2(0, 0);
    __syncwarp();

    int grp = lane >> 3;                               // edge within quad
    int sub = lane & 7;                                // dim chunk (8 dims)
    const uint4* srcl = (const uint4*)src + sub;

    #pragma unroll
    for (int k = 0; k < 8; k++) acc[k] = 0.f;

    int i = 0;
    for (; i + 7 < cnt; i += 8) {                      // 2 steps = 8 edges
        quad_step(srcl, sm, i,     grp, acc);
        quad_step(srcl, sm, i + 4, grp, acc);
    }
    for (; i < cnt; i += 4)                            // pad covers remainder
        quad_step(srcl, sm, i, grp, acc);
    __syncwarp();                                      // protect smem reuse

    // Merge the 4 edge-group partials (groups differ in lane bits 3-4).
    #pragma unroll
    for (int k = 0; k < 8; k++) {
        acc[k] += __shfl_xor_sync(0xffffffffu, acc[k], 8);
        acc[k] += __shfl_xor_sync(0xffffffffu, acc[k], 16);
    }
}

__global__ __launch_bounds__(256) void spmm_kernel(
    const __half* __restrict__ src,
    __half*       __restrict__ dst)
{
    __shared__ __align__(16) int2 s_meta[WARPS_PER_BLOCK][CAP + 4];
    int warp = (blockIdx.x * blockDim.x + threadIdx.x) >> 5;
    int lane = threadIdx.x & 31;
    if (warp >= N_NODES) return;
    float acc[8];
    row_segsum(src, s_meta[(threadIdx.x >> 5)], warp, lane, acc);
    if (lane < 8) {                                    // 8 lanes x 16B = row
        uint4 h;
        __half2 h01 = __floats2half2_rn(acc[0], acc[1]);
        __half2 h23 = __floats2half2_rn(acc[2], acc[3]);
        __half2 h45 = __floats2half2_rn(acc[4], acc[5]);
        __half2 h67 = __floats2half2_rn(acc[6], acc[7]);
        h.x = *(unsigned*)&h01;
        h.y = *(unsigned*)&h23;
        h.z = *(unsigned*)&h45;
        h.w = *(unsigned*)&h67;
        ((uint4*)dst)[(size_t)warp * (DIM / 8) + lane] = h;
    }
}

// Layer 3 + final combine: out = (e0_f32 + e1 + e2 + sum3) * 0.25
__global__ __launch_bounds__(256) void spmm_final_kernel(
    const __half* __restrict__ src,        // h2 (e2): gather source
    const float*  __restrict__ user_emb,
    const float*  __restrict__ item_emb,
    float*        __restrict__ out)
{
    __shared__ __align__(16) int2 s_meta[WARPS_PER_BLOCK][CAP + 4];
    int warp = (blockIdx.x * blockDim.x + threadIdx.x) >> 5;
    int lane = threadIdx.x & 31;
    if (warp >= N_NODES) return;
    float acc[8];
    row_segsum(src, s_meta[(threadIdx.x >> 5)], warp, lane, acc);

    if (lane < 8) {                                    // 8 dims per lane
        size_t o = (size_t)warp * (DIM / 8) + lane;    // uint4 index
        uint4 h1b = __ldg((const uint4*)g_h1 + o);
        uint4 h2b = __ldg((const uint4*)g_h2 + o);
        const unsigned* p1 = (const unsigned*)&h1b;
        const unsigned* p2 = (const unsigned*)&h2b;
        const float* inp = (warp < N_USERS)
            ? user_emb + (size_t)warp * DIM
            : item_emb + (size_t)(warp - N_USERS) * DIM;
        float4 e0a = __ldg((const float4*)inp + lane * 2);
        float4 e0b = __ldg((const float4*)inp + lane * 2 + 1);
        float e0[8] = {e0a.x, e0a.y, e0a.z, e0a.w,
                       e0b.x, e0b.y, e0b.z, e0b.w};
        float r[8];
        #pragma unroll
        for (int k = 0; k < 4; k++) {
            float2 e1 = __half22float2(*(const __half2*)&p1[k]);
            float2 e2 = __half22float2(*(const __half2*)&p2[k]);
            r[2*k]   = (e0[2*k]   + e1.x + e2.x + acc[2*k])   * 0.25f;
            r[2*k+1] = (e0[2*k+1] + e1.y + e2.y + acc[2*k+1]) * 0.25f;
        }
        float4* op = (float4*)out + (size_t)warp * (DIM / 4) + lane * 2;
        op[0] = make_float4(r[0], r[1], r[2], r[3]);
        op[1] = make_float4(r[4], r[5], r[6], r[7]);
    }
}

extern "C" void kernel_launch(void* const* d_in, const int* in_sizes, int n_in,
                              void* d_out, int out_size)
{
    const int*   rows     = (const int*)  d_in[0];
    const int*   cols     = (const int*)  d_in[1];
    const float* vals     = (const float*)d_in[2];
    const float* user_emb = (const float*)d_in[3];
    const float* item_emb = (const float*)d_in[4];
    float*       out      = (float*)d_out;

    __half *h0, *h1, *h2;
    cudaGetSymbolAddress((void**)&h0, g_h0);
    cudaGetSymbolAddress((void**)&h1, g_h1);
    cudaGetSymbolAddress((void**)&h2, g_h2);

    const int thr = 256;
    const int bucket_blocks = (NNZ / 4 + thr - 1) / thr;
    const int vec_blocks  = (int)((TOTAL4 + thr - 1) / thr);
    const int spmm_blocks = (int)(((long long)N_NODES * 32 + thr - 1) / thr);

    init_kernel<<<vec_blocks, thr>>>(user_emb, item_emb);
    bucket_kernel<<<bucket_blocks, thr>>>(rows, cols, vals);

    spmm_kernel<<<spmm_blocks, thr>>>(h0, h1);              // e1 = A e0
    spmm_kernel<<<spmm_blocks, thr>>>(h1, h2);              // e2 = A e1
    spmm_final_kernel<<<spmm_blocks, thr>>>(h2, user_emb, item_emb, out);
}

// round 16
// speedup vs baseline: 1.0248x; 1.0248x over previous
#include <cuda_runtime.h>
#include <cuda_fp16.h>

#define N_USERS 100000
#define N_ITEMS 200000
#define N_NODES (N_USERS + N_ITEMS)
#define NNZ     9600000
#define DIM     64
#define TOTAL   ((size_t)N_NODES * DIM)
#define TOTAL4  (TOTAL / 4)
#define CAP     128                     // slots/row; mean degree 32, ~17 sigma
#define WARPS_PER_BLOCK 8

// Scratch (__device__ globals, alloc-free rule).
// h0 = fp16(e0), h1 = e1, h2 = e2. Final combine reads fp32 inputs directly.
__device__ __align__(16) __half g_h0[TOTAL];
__device__ __align__(16) __half g_h1[TOTAL];
__device__ __align__(16) __half g_h2[TOTAL];
__device__ __align__(16) int2   g_bucket[(size_t)N_NODES * CAP];
__device__ int g_cnt[N_NODES];

// ---------------------------------------------------------------------------
// init: g_h0 = fp16(concat(user,item)); g_cnt = 0.
// ---------------------------------------------------------------------------
__global__ __launch_bounds__(256) void init_kernel(
    const float* __restrict__ user_emb,
    const float* __restrict__ item_emb)
{
    size_t i = (size_t)blockIdx.x * blockDim.x + threadIdx.x;
    if (i < N_NODES) g_cnt[i] = 0;
    if (i >= TOTAL4) return;
    const size_t ub = (size_t)N_USERS * DIM / 4;
    float4 v = (i < ub) ? ((const float4*)user_emb)[i]
                        : ((const float4*)item_emb)[i - ub];
    uint2 h;
    __half2 h01 = __floats2half2_rn(v.x, v.y);
    __half2 h23 = __floats2half2_rn(v.z, v.w);
    h.x = *(unsigned*)&h01;
    h.y = *(unsigned*)&h23;
    ((uint2*)g_h0)[i] = h;
}

// ---------------------------------------------------------------------------
// Single-pass bucketing, 4 edges/thread via int4 loads (NNZ % 4 == 0).
// Entry: (col, fp32 weight bits).
// ---------------------------------------------------------------------------
__global__ __launch_bounds__(256) void bucket_kernel(
    const int*   __restrict__ rows,
    const int*   __restrict__ cols,
    const float* __restrict__ vals)
{
    int t = blockIdx.x * blockDim.x + threadIdx.x;
    int e = t * 4;
    if (e >= NNZ) return;
    int4 r4 = __ldcs((const int4*)(rows + e));
    int4 c4 = __ldcs((const int4*)(cols + e));
    int4 v4 = __ldcs((const int4*)(vals + e));
    int rr[4] = {r4.x, r4.y, r4.z, r4.w};
    int cc[4] = {c4.x, c4.y, c4.z, c4.w};
    int vv[4] = {v4.x, v4.y, v4.z, v4.w};
    #pragma unroll
    for (int k = 0; k < 4; k++) {
        int pos = atomicAdd(&g_cnt[rr[k]], 1);
        if (pos < CAP)
            g_bucket[(size_t)rr[k] * CAP + pos] = make_int2(cc[k], vv[k]);
    }
}

// ---------------------------------------------------------------------------
// Warp-per-row segment sum, paired-edge gathers (R14 layout):
//  - meta staged in smem (+1 zero-weight pad entry for odd degrees)
//  - lanes 0-15 process even edges, lanes 16-31 odd edges; each lane gathers
//    uint2 (4 halfs = 4 dims) -> one warp LDG.64 covers TWO edges
//  - 16-edge unroll: 8 independent LDG.64s in flight per lane (deeper MLP
//    than R14's 4, no cross-iteration registers)
//  - fp32 float4 accumulator; shfl_xor(16) merges even/odd partials.
// ---------------------------------------------------------------------------
__device__ __forceinline__ void pair_step(
    const uint2* __restrict__ srcl, const int2* __restrict__ sm,
    int i, int half, float4& acc)
{
    int2 m = sm[i + half];                             // LDS.64, 2-way bcast
    uint2 x = __ldg(srcl + (size_t)m.x * (DIM / 4));   // 8B of row m.x
    float v = __int_as_float(m.y);
    float2 a = __half22float2(*(const __half2*)&x.x);
    float2 b = __half22float2(*(const __half2*)&x.y);
    acc.x = fmaf(a.x, v, acc.x);
    acc.y = fmaf(a.y, v, acc.y);
    acc.z = fmaf(b.x, v, acc.z);
    acc.w = fmaf(b.y, v, acc.w);
}

// Returns full row sum (all lanes) for dims [4*sub .. 4*sub+3], sub = lane&15.
__device__ __forceinline__ float4 row_segsum(
    const __half* __restrict__ src, int2* __restrict__ sm, int row, int lane)
{
    int cnt = __ldg(&g_cnt[row]);
    if (cnt > CAP) cnt = CAP;
    const int2* ep = g_bucket + (size_t)row * CAP;

    // Stage meta into smem (coalesced), then add a zero-weight pad entry so
    // the paired loop never needs an odd-tail branch.
    for (int b = lane; b < cnt; b += 32)
        sm[b] = __ldg(ep + b);
    if (lane == 0)
        sm[cnt] = make_int2(0, 0);
    __syncwarp();

    int half = lane >> 4;                              // which edge of a pair
    int sub  = lane & 15;                              // dim chunk (4 dims)
    const uint2* srcl = (const uint2*)src + sub;

    float4 acc = make_float4(0.f, 0.f, 0.f, 0.f);
    int i = 0;
    for (; i + 15 < cnt; i += 16) {                    // 8 steps = 16 edges
        pair_step(srcl, sm, i,      half, acc);
        pair_step(srcl, sm, i + 2,  half, acc);
        pair_step(srcl, sm, i + 4,  half, acc);
        pair_step(srcl, sm, i + 6,  half, acc);
        pair_step(srcl, sm, i + 8,  half, acc);
        pair_step(srcl, sm, i + 10, half, acc);
        pair_step(srcl, sm, i + 12, half, acc);
        pair_step(srcl, sm, i + 14, half, acc);
    }
    for (; i < cnt; i += 2)                            // pad covers odd cnt
        pair_step(srcl, sm, i, half, acc);
    __syncwarp();                                      // protect smem reuse

    // Merge even-edge (lanes 0-15) and odd-edge (16-31) partials.
    acc.x += __shfl_xor_sync(0xffffffffu, acc.x, 16);
    acc.y += __shfl_xor_sync(0xffffffffu, acc.y, 16);
    acc.z += __shfl_xor_sync(0xffffffffu, acc.z, 16);
    acc.w += __shfl_xor_sync(0xffffffffu, acc.w, 16);
    return acc;
}

__global__ __launch_bounds__(256) void spmm_kernel(
    const __half* __restrict__ src,
    __half*       __restrict__ dst)
{
    __shared__ __align__(16) int2 s_meta[WARPS_PER_BLOCK][CAP + 2];
    int warp = (blockIdx.x * blockDim.x + threadIdx.x) >> 5;
    int lane = threadIdx.x & 31;
    if (warp >= N_NODES) return;
    float4 sum = row_segsum(src, s_meta[(threadIdx.x >> 5)], warp, lane);
    if (lane < 16) {                                   // 16 lanes x 8B = row
        uint2 h;
        __half2 h01 = __floats2half2_rn(sum.x, sum.y);
        __half2 h23 = __floats2half2_rn(sum.z, sum.w);
        h.x = *(unsigned*)&h01;
        h.y = *(unsigned*)&h23;
        ((uint2*)dst)[(size_t)warp * (DIM / 4) + lane] = h;
    }
}

// Layer 3 + final combine: out = (e0_f32 + e1 + e2 + sum3) * 0.25
__global__ __launch_bounds__(256) void spmm_final_kernel(
    const __half* __restrict__ src,        // h2 (e2): gather source
    const float*  __restrict__ user_emb,
    const float*  __restrict__ item_emb,
    float*        __restrict__ out)
{
    __shared__ __align__(16) int2 s_meta[WARPS_PER_BLOCK][CAP + 2];
    int warp = (blockIdx.x * blockDim.x + threadIdx.x) >> 5;
    int lane = threadIdx.x & 31;
    if (warp >= N_NODES) return;
    float4 sum = row_segsum(src, s_meta[(threadIdx.x >> 5)], warp, lane);

    if (lane < 16) {                                   // 4 dims per lane
        size_t o = (size_t)warp * (DIM / 4) + lane;    // uint2 / float4 index
        uint2 h1b = __ldg((const uint2*)g_h1 + o);
        uint2 h2b = __ldg((const uint2*)g_h2 + o);
        float2 e1a = __half22float2(*(const __half2*)&h1b.x);
        float2 e1b = __half22float2(*(const __half2*)&h1b.y);
        float2 e2a = __half22float2(*(const __half2*)&h2b.x);
        float2 e2b = __half22float2(*(const __half2*)&h2b.y);
        const float* inp = (warp < N_USERS)
            ? user_emb + (size_t)warp * DIM
            : item_emb + (size_t)(warp - N_USERS) * DIM;
        float4 e0 = __ldg((const float4*)inp + lane);

        float4 r;
        r.x = (e0.x + e1a.x + e2a.x + sum.x) * 0.25f;
        r.y = (e0.y + e1a.y + e2a.y + sum.y) * 0.25f;
        r.z = (e0.z + e1b.x + e2b.x + sum.z) * 0.25f;
        r.w = (e0.w + e1b.y + e2b.y + sum.w) * 0.25f;
        ((float4*)out)[o] = r;
    }
}

extern "C" void kernel_launch(void* const* d_in, const int* in_sizes, int n_in,
                              void* d_out, int out_size)
{
    const int*   rows     = (const int*)  d_in[0];
    const int*   cols     = (const int*)  d_in[1];
    const float* vals     = (const float*)d_in[2];
    const float* user_emb = (const float*)d_in[3];
    const float* item_emb = (const float*)d_in[4];
    float*       out      = (float*)d_out;

    __half *h0, *h1, *h2;
    cudaGetSymbolAddress((void**)&h0, g_h0);
    cudaGetSymbolAddress((void**)&h1, g_h1);
    cudaGetSymbolAddress((void**)&h2, g_h2);

    const int thr = 256;
    const int bucket_blocks = (NNZ / 4 + thr - 1) / thr;
    const int vec_blocks  = (int)((TOTAL4 + thr - 1) / thr);
    const int spmm_blocks = (int)(((long long)N_NODES * 32 + thr - 1) / thr);

    init_kernel<<<vec_blocks, thr>>>(user_emb, item_emb);
    bucket_kernel<<<bucket_blocks, thr>>>(rows, cols, vals);

    spmm_kernel<<<spmm_blocks, thr>>>(h0, h1);              // e1 = A e0
    spmm_kernel<<<spmm_blocks, thr>>>(h1, h2);              // e2 = A e1
    spmm_final_kernel<<<spmm_blocks, thr>>>(h2, user_emb, item_emb, out);
}

// round 17
// speedup vs baseline: 1.0908x; 1.0644x over previous
#include <cuda_runtime.h>
#include <cuda_fp16.h>

#define N_USERS 100000
#define N_ITEMS 200000
#define N_NODES (N_USERS + N_ITEMS)
#define NNZ     9600000
#define DIM     64
#define TOTAL   ((size_t)N_NODES * DIM)
#define TOTAL4  (TOTAL / 4)
#define CAP     128                     // slots/row; mean degree 32, ~17 sigma
#define WARPS_PER_BLOCK 8

// Scratch (__device__ globals, alloc-free rule).
// h0 = fp16(e0), h1 = e1, h2 = e2. Final combine reads fp32 inputs directly.
// g_cnt is zero-initialized at load and re-zeroed at the END of every call
// (tail of spmm_final), so bucket_kernel's precondition holds on every call.
__device__ __align__(16) __half g_h0[TOTAL];
__device__ __align__(16) __half g_h1[TOTAL];
__device__ __align__(16) __half g_h2[TOTAL];
__device__ __align__(16) int2   g_bucket[(size_t)N_NODES * CAP];
__device__ int g_cnt[N_NODES];

// ---------------------------------------------------------------------------
// h0 init: g_h0 = fp16(concat(user,item)). Independent of bucketing ->
// runs on a second stream, overlapped with bucket_kernel.
// ---------------------------------------------------------------------------
__global__ __launch_bounds__(256) void h0_init_kernel(
    const float* __restrict__ user_emb,
    const float* __restrict__ item_emb)
{
    size_t i = (size_t)blockIdx.x * blockDim.x + threadIdx.x;
    if (i >= TOTAL4) return;
    const size_t ub = (size_t)N_USERS * DIM / 4;
    float4 v = (i < ub) ? ((const float4*)user_emb)[i]
                        : ((const float4*)item_emb)[i - ub];
    uint2 h;
    __half2 h01 = __floats2half2_rn(v.x, v.y);
    __half2 h23 = __floats2half2_rn(v.z, v.w);
    h.x = *(unsigned*)&h01;
    h.y = *(unsigned*)&h23;
    ((uint2*)g_h0)[i] = h;
}

// ---------------------------------------------------------------------------
// Single-pass bucketing, 4 edges/thread via int4 loads (NNZ % 4 == 0).
// Entry: (col, fp32 weight bits). Requires g_cnt == 0 (invariant).
// ---------------------------------------------------------------------------
__global__ __launch_bounds__(256) void bucket_kernel(
    const int*   __restrict__ rows,
    const int*   __restrict__ cols,
    const float* __restrict__ vals)
{
    int t = blockIdx.x * blockDim.x + threadIdx.x;
    int e = t * 4;
    if (e >= NNZ) return;
    int4 r4 = __ldcs((const int4*)(rows + e));
    int4 c4 = __ldcs((const int4*)(cols + e));
    int4 v4 = __ldcs((const int4*)(vals + e));
    int rr[4] = {r4.x, r4.y, r4.z, r4.w};
    int cc[4] = {c4.x, c4.y, c4.z, c4.w};
    int vv[4] = {v4.x, v4.y, v4.z, v4.w};
    #pragma unroll
    for (int k = 0; k < 4; k++) {
        int pos = atomicAdd(&g_cnt[rr[k]], 1);
        if (pos < CAP)
            g_bucket[(size_t)rr[k] * CAP + pos] = make_int2(cc[k], vv[k]);
    }
}

// ---------------------------------------------------------------------------
// Warp-per-row segment sum, paired-edge gathers (R14 layout, unchanged):
//  - meta staged in smem (+1 zero-weight pad entry for odd degrees)
//  - lanes 0-15 process even edges, lanes 16-31 odd edges; each lane gathers
//    uint2 (4 halfs = 4 dims) -> one warp LDG.64 covers TWO edges
//  - 8-edge unroll (4 pair_steps); fp32 float4 accumulator;
//    shfl_xor(16) merges even/odd partials.
// ---------------------------------------------------------------------------
__device__ __forceinline__ void pair_step(
    const uint2* __restrict__ srcl, const int2* __restrict__ sm,
    int i, int half, float4& acc)
{
    int2 m = sm[i + half];                             // LDS.64, 2-way bcast
    uint2 x = __ldg(srcl + (size_t)m.x * (DIM / 4));   // 8B of row m.x
    float v = __int_as_float(m.y);
    float2 a = __half22float2(*(const __half2*)&x.x);
    float2 b = __half22float2(*(const __half2*)&x.y);
    acc.x = fmaf(a.x, v, acc.x);
    acc.y = fmaf(a.y, v, acc.y);
    acc.z = fmaf(b.x, v, acc.z);
    acc.w = fmaf(b.y, v, acc.w);
}

// Returns full row sum (all lanes) for dims [4*sub .. 4*sub+3], sub = lane&15.
__device__ __forceinline__ float4 row_segsum(
    const __half* __restrict__ src, int2* __restrict__ sm, int row, int lane)
{
    int cnt = __ldg(&g_cnt[row]);
    if (cnt > CAP) cnt = CAP;
    const int2* ep = g_bucket + (size_t)row * CAP;

    // Stage meta into smem (coalesced), then add a zero-weight pad entry so
    // the paired loop never needs an odd-tail branch.
    for (int b = lane; b < cnt; b += 32)
        sm[b] = __ldg(ep + b);
    if (lane == 0)
        sm[cnt] = make_int2(0, 0);
    __syncwarp();

    int half = lane >> 4;                              // which edge of a pair
    int sub  = lane & 15;                              // dim chunk (4 dims)
    const uint2* srcl = (const uint2*)src + sub;

    float4 acc = make_float4(0.f, 0.f, 0.f, 0.f);
    int i = 0;
    for (; i + 7 < cnt; i += 8) {                      // 4 steps = 8 edges
        pair_step(srcl, sm, i,     half, acc);
        pair_step(srcl, sm, i + 2, half, acc);
        pair_step(srcl, sm, i + 4, half, acc);
        pair_step(srcl, sm, i + 6, half, acc);
    }
    for (; i < cnt; i += 2)                            // pad covers odd cnt
        pair_step(srcl, sm, i, half, acc);
    __syncwarp();                                      // protect smem reuse

    // Merge even-edge (lanes 0-15) and odd-edge (16-31) partials.
    acc.x += __shfl_xor_sync(0xffffffffu, acc.x, 16);
    acc.y += __shfl_xor_sync(0xffffffffu, acc.y, 16);
    acc.z += __shfl_xor_sync(0xffffffffu, acc.z, 16);
    acc.w += __shfl_xor_sync(0xffffffffu, acc.w, 16);
    return acc;
}

__global__ __launch_bounds__(256) void spmm_kernel(
    const __half* __restrict__ src,
    __half*       __restrict__ dst)
{
    __shared__ __align__(16) int2 s_meta[WARPS_PER_BLOCK][CAP + 2];
    int warp = (blockIdx.x * blockDim.x + threadIdx.x) >> 5;
    int lane = threadIdx.x & 31;
    if (warp >= N_NODES) return;
    float4 sum = row_segsum(src, s_meta[(threadIdx.x >> 5)], warp, lane);
    if (lane < 16) {                                   // 16 lanes x 8B = row
        uint2 h;
        __half2 h01 = __floats2half2_rn(sum.x, sum.y);
        __half2 h23 = __floats2half2_rn(sum.z, sum.w);
        h.x = *(unsigned*)&h01;
        h.y = *(unsigned*)&h23;
        ((uint2*)dst)[(size_t)warp * (DIM / 4) + lane] = h;
    }
}

// Layer 3 + final combine: out = (e0_f32 + e1 + e2 + sum3) * 0.25.
// Also resets this row's counter (last reader) so the next call's
// bucket_kernel sees g_cnt == 0 without a separate zeroing kernel.
__global__ __launch_bounds__(256) void spmm_final_kernel(
    const __half* __restrict__ src,        // h2 (e2): gather source
    const float*  __restrict__ user_emb,
    const float*  __restrict__ item_emb,
    float*        __restrict__ out)
{
    __shared__ __align__(16) int2 s_meta[WARPS_PER_BLOCK][CAP + 2];
    int warp = (blockIdx.x * blockDim.x + threadIdx.x) >> 5;
    int lane = threadIdx.x & 31;
    if (warp >= N_NODES) return;
    float4 sum = row_segsum(src, s_meta[(threadIdx.x >> 5)], warp, lane);

    if (lane == 31)                                    // restore invariant
        g_cnt[warp] = 0;

    if (lane < 16) {                                   // 4 dims per lane
        size_t o = (size_t)warp * (DIM / 4) + lane;    // uint2 / float4 index
        uint2 h1b = __ldg((const uint2*)g_h1 + o);
        uint2 h2b = __ldg((const uint2*)g_h2 + o);
        float2 e1a = __half22float2(*(const __half2*)&h1b.x);
        float2 e1b = __half22float2(*(const __half2*)&h1b.y);
        float2 e2a = __half22float2(*(const __half2*)&h2b.x);
        float2 e2b = __half22float2(*(const __half2*)&h2b.y);
        const float* inp = (warp < N_USERS)
            ? user_emb + (size_t)warp * DIM
            : item_emb + (size_t)(warp - N_USERS) * DIM;
        float4 e0 = __ldg((const float4*)inp + lane);

        float4 r;
        r.x = (e0.x + e1a.x + e2a.x + sum.x) * 0.25f;
        r.y = (e0.y + e1a.y + e2a.y + sum.y) * 0.25f;
        r.z = (e0.z + e1b.x + e2b.x + sum.z) * 0.25f;
        r.w = (e0.w + e1b.y + e2b.y + sum.w) * 0.25f;
        ((float4*)out)[o] = r;
    }
}

extern "C" void kernel_launch(void* const* d_in, const int* in_sizes, int n_in,
                              void* d_out, int out_size)
{
    const int*   rows     = (const int*)  d_in[0];
    const int*   cols     = (const int*)  d_in[1];
    const float* vals     = (const float*)d_in[2];
    const float* user_emb = (const float*)d_in[3];
    const float* item_emb = (const float*)d_in[4];
    float*       out      = (float*)d_out;

    __half *h0, *h1, *h2;
    cudaGetSymbolAddress((void**)&h0, g_h0);
    cudaGetSymbolAddress((void**)&h1, g_h1);
    cudaGetSymbolAddress((void**)&h2, g_h2);

    // Side stream + events, created once on the first (uncaptured) call.
    // No device memory is allocated; event record/wait are capturable and
    // express the fork/join as graph dependencies.
    static cudaStream_t s_b = nullptr;
    static cudaEvent_t  ev_fork = nullptr, ev_join = nullptr;
    if (s_b == nullptr) {
        cudaStreamCreateWithFlags(&s_b, cudaStreamNonBlocking);
        cudaEventCreateWithFlags(&ev_fork, cudaEventDisableTiming);
        cudaEventCreateWithFlags(&ev_join, cudaEventDisableTiming);
    }

    const int thr = 256;
    const int bucket_blocks = (NNZ / 4 + thr - 1) / thr;
    const int vec_blocks  = (int)((TOTAL4 + thr - 1) / thr);
    const int spmm_blocks = (int)(((long long)N_NODES * 32 + thr - 1) / thr);

    // Fork: h0 conversion runs on s_b, overlapped with bucketing on the
    // main stream (they touch disjoint state; g_cnt is already 0).
    cudaEventRecord(ev_fork, 0);
    cudaStreamWaitEvent(s_b, ev_fork, 0);
    h0_init_kernel<<<vec_blocks, thr, 0, s_b>>>(user_emb, item_emb);
    cudaEventRecord(ev_join, s_b);

    bucket_kernel<<<bucket_blocks, thr>>>(rows, cols, vals);

    // Join: spmm1 needs both h0 and the buckets.
    cudaStreamWaitEvent(0, ev_join, 0);

    spmm_kernel<<<spmm_blocks, thr>>>(h0, h1);              // e1 = A e0
    spmm_kernel<<<spmm_blocks, thr>>>(h1, h2);              // e2 = A e1
    spmm_final_kernel<<<spmm_blocks, thr>>>(h2, user_emb, item_emb, out);
}